// round 4
// baseline (speedup 1.0000x reference)
#include <cuda_runtime.h>
#include <cuda_bf16.h>
#include <cstdint>

#define BSZ   8
#define NROI  64
#define HDIM  512
#define NLAYER 5
#define BI    (BSZ*NROI)                     // 512 (b,i) pairs

// ---------------- scratch (device globals; no allocation allowed) ----------
__device__ __nv_bfloat16 g_ebuf[2][(size_t)BSZ*NROI*NROI*HDIM]; // ping-pong edge_state (bf16)
__device__ __nv_bfloat16 g_eW16[(size_t)NLAYER*HDIM*HDIM];      // bf16 edge weights
__device__ float g_nm[BI*HDIM];
__device__ float g_ns[BI*HDIM];
__device__ float g_denom[BI];
__device__ float g_em0[BSZ*HDIM];                       // layer-0 edge matvec (incl. bias)
__device__ float g_e0[BSZ*HDIM];                        // mean of img_featmap

__device__ __forceinline__ float leaky(float x) { return x >= 0.f ? x : 0.01f * x; }
__device__ __forceinline__ unsigned smem_u32(const void* p) {
    return (unsigned)__cvta_generic_to_shared(p);
}
__device__ __forceinline__ void cpa16(unsigned dst, const void* src) {
    asm volatile("cp.async.ca.shared.global [%0], [%1], 16;" :: "r"(dst), "l"(src));
}

// ---------------- prep: node_state copy, e0 mean, denom --------------------
__global__ void prep_kernel(const float* __restrict__ roi,
                            const float* __restrict__ img,
                            const int*  __restrict__ mask) {
    int idx = blockIdx.x * blockDim.x + threadIdx.x;
    int total = blockDim.x * gridDim.x;
    for (int i = idx; i < BI*HDIM; i += total) g_ns[i] = roi[i];
    if (idx < BSZ*HDIM) {
        const float* p = img + (size_t)idx * 196;
        float s = 0.f;
        #pragma unroll 4
        for (int q = 0; q < 196; q++) s += p[q];
        g_e0[idx] = s * (1.0f/196.0f);
    }
    if (idx < BI) {
        const int* m = mask + idx * NROI;
        int s = 0;
        #pragma unroll
        for (int j = 0; j < NROI; j++) s += m[j];
        g_denom[idx] = (float)s + 1.0f;
    }
}

// ---------------- convert edge weights to bf16 (vectorized) -----------------
__global__ void convW_kernel(const float* __restrict__ eW) {
    int i = blockIdx.x * blockDim.x + threadIdx.x;
    if (i < NLAYER*HDIM*HDIM/2) {
        float2 v = ((const float2*)eW)[i];
        ((__nv_bfloat162*)g_eW16)[i] = __floats2bfloat162_rn(v.x, v.y);
    }
}

// ---------------- nm GEMM: g_nm = g_ns @ node_W[t]^T + node_b[t] (fp32) -----
__global__ void nm_kernel(const float* __restrict__ Wt,
                          const float* __restrict__ bt) {
    __shared__ float As[16][68];
    __shared__ float Ws[16][68];
    int tid = threadIdx.x;
    int tx = tid & 15, ty = tid >> 4;
    int r0 = blockIdx.y * 64, c0 = blockIdx.x * 64;
    const float* A = g_ns + (size_t)r0 * HDIM;
    const float* W = Wt   + (size_t)c0 * HDIM;
    float acc[4][4] = {};
    int lrow = tid >> 2;
    int lk   = (tid & 3) * 4;
    for (int k0 = 0; k0 < HDIM; k0 += 16) {
        float4 a = *(const float4*)(A + (size_t)lrow*HDIM + k0 + lk);
        float4 w = *(const float4*)(W + (size_t)lrow*HDIM + k0 + lk);
        As[lk+0][lrow]=a.x; As[lk+1][lrow]=a.y; As[lk+2][lrow]=a.z; As[lk+3][lrow]=a.w;
        Ws[lk+0][lrow]=w.x; Ws[lk+1][lrow]=w.y; Ws[lk+2][lrow]=w.z; Ws[lk+3][lrow]=w.w;
        __syncthreads();
        #pragma unroll
        for (int k = 0; k < 16; k++) {
            float4 av = *(const float4*)&As[k][ty*4];
            float4 wv = *(const float4*)&Ws[k][tx*4];
            float ar[4] = {av.x, av.y, av.z, av.w};
            float wr[4] = {wv.x, wv.y, wv.z, wv.w};
            #pragma unroll
            for (int r = 0; r < 4; r++)
                #pragma unroll
                for (int c = 0; c < 4; c++)
                    acc[r][c] += ar[r] * wr[c];
        }
        __syncthreads();
    }
    float4 bv = *(const float4*)(bt + c0 + tx*4);
    float bb[4] = {bv.x, bv.y, bv.z, bv.w};
    #pragma unroll
    for (int r = 0; r < 4; r++) {
        int row = r0 + ty*4 + r;
        float4 o;
        o.x = acc[r][0] + bb[0];
        o.y = acc[r][1] + bb[1];
        o.z = acc[r][2] + bb[2];
        o.w = acc[r][3] + bb[3];
        *(float4*)(g_nm + (size_t)row*HDIM + c0 + tx*4) = o;
    }
}

// ---------------- layer-0 edge matvec (float4 vectorized) -------------------
__global__ void em0_kernel(const float* __restrict__ W0,
                           const float* __restrict__ eb0) {
    int warp = (blockIdx.x * blockDim.x + threadIdx.x) >> 5;
    int lane = threadIdx.x & 31;
    if (warp >= BSZ*HDIM) return;
    int b = warp >> 9;
    int o = warp & 511;
    const float4* e4 = (const float4*)(g_e0 + b*HDIM);
    const float4* w4 = (const float4*)(W0 + (size_t)o*HDIM);
    float s = 0.f;
    #pragma unroll
    for (int it = 0; it < 4; it++) {
        float4 e = e4[lane + it*32];
        float4 w = w4[lane + it*32];
        s += e.x*w.x + e.y*w.y + e.z*w.z + e.w*w.w;
    }
    #pragma unroll
    for (int d = 16; d; d >>= 1) s += __shfl_xor_sync(0xffffffffu, s, d);
    if (lane == 0) g_em0[warp] = s + eb0[o];
}

// ---------------- layer-0 fused edge (no GEMM) + node update ----------------
__global__ void edge0_kernel(const int* __restrict__ mask) {
    int bi = blockIdx.x;
    int b  = bi >> 6;
    const float* nmB = g_nm + (size_t)b * NROI * HDIM;
    const float* nmi = g_nm + (size_t)bi * HDIM;
    __nv_bfloat16* dstp = g_ebuf[0] + (size_t)bi * NROI * HDIM;
    int o1 = threadIdx.x, o2 = threadIdx.x + 256;
    float nmv1 = nmi[o1], nmv2 = nmi[o2];
    float base1 = nmv1 + g_em0[b*HDIM + o1];
    float base2 = nmv2 + g_em0[b*HDIM + o2];
    float agg1 = 0.f, agg2 = 0.f;
    for (int j = 0; j < NROI; j++) {
        float m = (float)mask[bi*NROI + j];
        float nj1 = nmB[j*HDIM + o1];
        float nj2 = nmB[j*HDIM + o2];
        float e1 = leaky(base1 + nj1);
        float e2 = leaky(base2 + nj2);
        dstp[j*HDIM + o1] = __float2bfloat16(e1);
        dstp[j*HDIM + o2] = __float2bfloat16(e2);
        agg1 += e1 * nj1 * m;
        agg2 += e2 * nj2 * m;
    }
    float dn = g_denom[bi];
    g_ns[(size_t)bi*HDIM + o1] += leaky((nmv1 + agg1) / dn);
    g_ns[(size_t)bi*HDIM + o2] += leaky((nmv2 + agg2) / dn);
}

// ---------------- fused edge GEMM (layers 1..4), bf16 MMA, cp.async ---------
// Block: bi pair (2 adjacent (b,i)), o-tile 128. GEMM 128(m=2x64 j) x 128(o) x 512(k).
// 2-stage cp.async double buffer, k-chunk 32. Fused epilogue: leaky + bf16
// edge write + masked agg reduction + node_state update.
#define KC    32
#define NIT   (HDIM/KC)     // 16
#define STRD  40            // smem row stride (elems), conflict-free, 16B-aligned

__global__ __launch_bounds__(256, 2) void edge_mma_kernel(
    int t, const float* __restrict__ ebt, const int* __restrict__ mask,
    int src, int dst, int writeEdge)
{
    __shared__ __nv_bfloat16 As[2][128*STRD];
    __shared__ __nv_bfloat16 Bs[2][128*STRD];
    __shared__ float aggsm[4][128];

    int tid  = threadIdx.x;
    int wid  = tid >> 5, lane = tid & 31;
    int wm   = wid & 3;        // 4 warps over m (32 rows each)
    int wn   = wid >> 2;       // 2 warps over n (64 cols each)
    int biPair = blockIdx.y;   // 0..255
    int bi0  = biPair * 2;
    int b    = bi0 >> 6;
    int o0   = blockIdx.x * 128;

    const __nv_bfloat16* W16 = g_eW16 + (size_t)t * HDIM * HDIM;
    const __nv_bfloat16* A   = g_ebuf[src] + (size_t)bi0 * NROI * HDIM; // 128 contiguous rows
    const __nv_bfloat16* Bw  = W16 + (size_t)o0 * HDIM;                 // [o][k]

    float acc[2][8][4] = {};

    // cp.async indices: each thread copies 32B of A and 32B of B per stage
    int lrow = tid >> 1;               // 0..127
    int lcb  = (tid & 1) * 16;         // 0 or 16 (elems)

    // prologue: stage 0
    {
        unsigned sA = smem_u32(&As[0][lrow*STRD + lcb]);
        const __nv_bfloat16* gA = A + (size_t)lrow*HDIM + lcb;
        cpa16(sA, gA); cpa16(sA+16, gA+8);
        unsigned sB = smem_u32(&Bs[0][lrow*STRD + lcb]);
        const __nv_bfloat16* gB = Bw + (size_t)lrow*HDIM + lcb;
        cpa16(sB, gB); cpa16(sB+16, gB+8);
        asm volatile("cp.async.commit_group;");
    }

    for (int it = 0; it < NIT; it++) {
        if (it + 1 < NIT) {
            int st = (it + 1) & 1;
            int k0 = (it + 1) * KC;
            unsigned sA = smem_u32(&As[st][lrow*STRD + lcb]);
            const __nv_bfloat16* gA = A + (size_t)lrow*HDIM + k0 + lcb;
            cpa16(sA, gA); cpa16(sA+16, gA+8);
            unsigned sB = smem_u32(&Bs[st][lrow*STRD + lcb]);
            const __nv_bfloat16* gB = Bw + (size_t)lrow*HDIM + k0 + lcb;
            cpa16(sB, gB); cpa16(sB+16, gB+8);
            asm volatile("cp.async.commit_group;");
            asm volatile("cp.async.wait_group 1;");
        } else {
            asm volatile("cp.async.wait_group 0;");
        }
        __syncthreads();

        int st = it & 1;
        unsigned aBase = smem_u32(&As[st][(wm*32 + (lane & 15))*STRD + (lane >> 4)*8]);
        unsigned bBase = smem_u32(&Bs[st][(wn*64 + ((lane >> 4) << 3) + (lane & 7))*STRD
                                          + (((lane >> 3) & 1) << 3)]);
        #pragma unroll
        for (int ks = 0; ks < KC; ks += 16) {
            unsigned a[2][4];
            #pragma unroll
            for (int mf = 0; mf < 2; mf++) {
                asm volatile("ldmatrix.sync.aligned.m8n8.x4.shared.b16 {%0,%1,%2,%3},[%4];"
                    : "=r"(a[mf][0]),"=r"(a[mf][1]),"=r"(a[mf][2]),"=r"(a[mf][3])
                    : "r"(aBase + (unsigned)((mf*16*STRD + ks) * 2)));
            }
            #pragma unroll
            for (int p2 = 0; p2 < 4; p2++) {
                unsigned b0,b1,b2,b3;
                asm volatile("ldmatrix.sync.aligned.m8n8.x4.shared.b16 {%0,%1,%2,%3},[%4];"
                    : "=r"(b0),"=r"(b1),"=r"(b2),"=r"(b3)
                    : "r"(bBase + (unsigned)((p2*16*STRD + ks) * 2)));
                #pragma unroll
                for (int mf = 0; mf < 2; mf++) {
                    float* c0 = acc[mf][p2*2];
                    asm volatile("mma.sync.aligned.m16n8k16.row.col.f32.bf16.bf16.f32 "
                        "{%0,%1,%2,%3},{%4,%5,%6,%7},{%8,%9},{%0,%1,%2,%3};"
                        : "+f"(c0[0]),"+f"(c0[1]),"+f"(c0[2]),"+f"(c0[3])
                        : "r"(a[mf][0]),"r"(a[mf][1]),"r"(a[mf][2]),"r"(a[mf][3]),
                          "r"(b0),"r"(b1));
                    float* c1 = acc[mf][p2*2+1];
                    asm volatile("mma.sync.aligned.m16n8k16.row.col.f32.bf16.bf16.f32 "
                        "{%0,%1,%2,%3},{%4,%5,%6,%7},{%8,%9},{%0,%1,%2,%3};"
                        : "+f"(c1[0]),"+f"(c1[1]),"+f"(c1[2]),"+f"(c1[3])
                        : "r"(a[mf][0]),"r"(a[mf][1]),"r"(a[mf][2]),"r"(a[mf][3]),
                          "r"(b2),"r"(b3));
                }
            }
        }
        __syncthreads();
    }

    // ---- fused epilogue ----
    int bi_r = bi0 + (wm >> 1);                 // this warp's (b,i)
    const float* nmB = g_nm + (size_t)b * NROI * HDIM;
    const float* nmi = g_nm + (size_t)bi_r * HDIM;
    __nv_bfloat16* dstp = g_ebuf[dst] + (size_t)bi_r * NROI * HDIM;

    // row indices / masks per m-fragment
    int   jj[2][2];
    float mm[2][2];
    #pragma unroll
    for (int mf = 0; mf < 2; mf++) {
        int row = wm*32 + mf*16 + (lane >> 2);
        int j1 = row & 63;
        jj[mf][0] = j1; jj[mf][1] = j1 + 8;
        mm[mf][0] = (float)mask[bi_r*NROI + j1];
        mm[mf][1] = (float)mask[bi_r*NROI + j1 + 8];
    }

    #pragma unroll
    for (int p = 0; p < 8; p++) {
        int o = o0 + wn*64 + p*8 + (lane & 3)*2;
        float2 ni  = *(const float2*)(nmi + o);
        float2 ebv = *(const float2*)(ebt + o);
        float bx = ni.x + ebv.x, by = ni.y + ebv.y;
        float s0 = 0.f, s1 = 0.f;
        #pragma unroll
        for (int mf = 0; mf < 2; mf++) {
            int j1 = jj[mf][0], j2 = jj[mf][1];
            float m1 = mm[mf][0], m2 = mm[mf][1];
            float2 nj1 = *(const float2*)(nmB + (size_t)j1*HDIM + o);
            float2 nj2 = *(const float2*)(nmB + (size_t)j2*HDIM + o);
            float e00 = leaky(acc[mf][p][0] + bx + nj1.x);
            float e01 = leaky(acc[mf][p][1] + by + nj1.y);
            float e10 = leaky(acc[mf][p][2] + bx + nj2.x);
            float e11 = leaky(acc[mf][p][3] + by + nj2.y);
            if (writeEdge) {
                __nv_bfloat162 v1; v1.x = __float2bfloat16(e00); v1.y = __float2bfloat16(e01);
                __nv_bfloat162 v2; v2.x = __float2bfloat16(e10); v2.y = __float2bfloat16(e11);
                *(__nv_bfloat162*)(dstp + (size_t)j1*HDIM + o) = v1;
                *(__nv_bfloat162*)(dstp + (size_t)j2*HDIM + o) = v2;
            }
            s0 += e00*nj1.x*m1 + e10*nj2.x*m2;
            s1 += e01*nj1.y*m1 + e11*nj2.y*m2;
        }
        #pragma unroll
        for (int d = 4; d <= 16; d <<= 1) {
            s0 += __shfl_xor_sync(0xffffffffu, s0, d);
            s1 += __shfl_xor_sync(0xffffffffu, s1, d);
        }
        if (lane < 4) {
            int oc = wn*64 + p*8 + lane*2;
            aggsm[wm][oc]   = s0;
            aggsm[wm][oc+1] = s1;
        }
    }
    __syncthreads();

    // block reduce over warp halves + fused node update
    {
        int bi_sel = tid >> 7;          // 0 or 1
        int oc = tid & 127;
        float aggv = aggsm[2*bi_sel][oc] + aggsm[2*bi_sel+1][oc];
        int bi2 = bi0 + bi_sel;
        int oo = o0 + oc;
        float nmv = g_nm[(size_t)bi2*HDIM + oo];
        float x = (nmv + aggv) / g_denom[bi2];
        g_ns[(size_t)bi2*HDIM + oo] += leaky(x);
    }
}

// ---------------- output: concat broadcast of node_state --------------------
__global__ void out_kernel(float* __restrict__ out) {
    size_t f = (size_t)blockIdx.x * blockDim.x + threadIdx.x;
    size_t total4 = (size_t)BSZ*NROI*NROI*1024 / 4;
    if (f >= total4) return;
    size_t flat = f * 4;
    int c = (int)(flat & 1023);
    size_t bij = flat >> 10;
    int j = (int)(bij & 63);
    size_t bi = bij >> 6;            // b*64+i
    size_t b  = bi >> 6;
    const float* src = (c < 512)
        ? (g_ns + bi * HDIM + c)
        : (g_ns + (b*64 + j) * HDIM + (c - 512));
    *(float4*)(out + flat) = *(const float4*)src;
}

// ---------------- host launch ------------------------------------------------
extern "C" void kernel_launch(void* const* d_in, const int* in_sizes, int n_in,
                              void* d_out, int out_size) {
    const float* roi = (const float*)d_in[0];
    const float* img = (const float*)d_in[1];
    const float* nW  = (const float*)d_in[2];
    const float* nb  = (const float*)d_in[3];
    const float* eW  = (const float*)d_in[4];
    const float* eb  = (const float*)d_in[5];
    const int*   msk = (const int*)d_in[6];
    float* out = (float*)d_out;

    prep_kernel<<<512, 256>>>(roi, img, msk);
    convW_kernel<<<(NLAYER*HDIM*HDIM/2 + 255)/256, 256>>>(eW);

    for (int t = 0; t < NLAYER; t++) {
        nm_kernel<<<dim3(8, 8), 256>>>(nW + (size_t)t*HDIM*HDIM, nb + (size_t)t*HDIM);
        if (t == 0) {
            em0_kernel<<<512, 256>>>(eW, eb);
            edge0_kernel<<<512, 256>>>(msk);
        } else {
            int dst = t & 1;
            int src = dst ^ 1;
            int we  = (t < NLAYER - 1) ? 1 : 0;   // last layer's edge_state unused
            edge_mma_kernel<<<dim3(4, 256), 256>>>(
                t, eb + (size_t)t*HDIM, msk, src, dst, we);
        }
    }

    out_kernel<<<32768, 256>>>(out);
}

// round 5
// speedup vs baseline: 1.5306x; 1.5306x over previous
#include <cuda_runtime.h>
#include <cuda_bf16.h>
#include <cstdint>

#define BSZ   8
#define NROI  64
#define HDIM  512
#define NLAYER 5
#define BI    (BSZ*NROI)                     // 512 (b,i) pairs

// ---------------- scratch (device globals; no allocation allowed) ----------
__device__ __nv_bfloat16 g_ebuf[2][(size_t)BSZ*NROI*NROI*HDIM]; // ping-pong edge_state (bf16)
__device__ __nv_bfloat16 g_eW16[(size_t)NLAYER*HDIM*HDIM];      // bf16 edge weights
__device__ __nv_bfloat16 g_nW16[(size_t)NLAYER*HDIM*HDIM];      // bf16 node weights
__device__ __nv_bfloat16 g_ns16[BI*HDIM];               // bf16 mirror of node_state
__device__ float g_nm[BI*HDIM];
__device__ float g_ns[BI*HDIM];
__device__ float g_denom[BI];
__device__ float g_em0[BSZ*HDIM];                       // layer-0 edge matvec (incl. bias)
__device__ float g_e0[BSZ*HDIM];                        // mean of img_featmap

__device__ __forceinline__ float leaky(float x) { return x >= 0.f ? x : 0.01f * x; }
__device__ __forceinline__ unsigned smem_u32(const void* p) {
    return (unsigned)__cvta_generic_to_shared(p);
}
__device__ __forceinline__ void cpa16(unsigned dst, const void* src) {
    asm volatile("cp.async.ca.shared.global [%0], [%1], 16;" :: "r"(dst), "l"(src));
}

// ---------------- prep: node_state copy (+bf16), e0 mean, denom -------------
__global__ void prep_kernel(const float* __restrict__ roi,
                            const float* __restrict__ img,
                            const int*  __restrict__ mask) {
    int idx = blockIdx.x * blockDim.x + threadIdx.x;
    int total = blockDim.x * gridDim.x;
    for (int i = idx; i < BI*HDIM; i += total) {
        float v = roi[i];
        g_ns[i] = v;
        g_ns16[i] = __float2bfloat16(v);
    }
    if (idx < BSZ*HDIM) {
        const float* p = img + (size_t)idx * 196;
        float s = 0.f;
        #pragma unroll 4
        for (int q = 0; q < 196; q++) s += p[q];
        g_e0[idx] = s * (1.0f/196.0f);
    }
    if (idx < BI) {
        const int* m = mask + idx * NROI;
        int s = 0;
        #pragma unroll
        for (int j = 0; j < NROI; j++) s += m[j];
        g_denom[idx] = (float)s + 1.0f;
    }
}

// ---------------- convert edge + node weights to bf16 -----------------------
__global__ void convW_kernel(const float* __restrict__ eW,
                             const float* __restrict__ nW) {
    int i = blockIdx.x * blockDim.x + threadIdx.x;
    const int half = NLAYER*HDIM*HDIM/2;
    if (i < half) {
        float2 v = ((const float2*)eW)[i];
        ((__nv_bfloat162*)g_eW16)[i] = __floats2bfloat162_rn(v.x, v.y);
    } else if (i < 2*half) {
        float2 v = ((const float2*)nW)[i - half];
        ((__nv_bfloat162*)g_nW16)[i - half] = __floats2bfloat162_rn(v.x, v.y);
    }
}

// ---------------- layer-0 edge matvec (float4 vectorized) -------------------
__global__ void em0_kernel(const float* __restrict__ W0,
                           const float* __restrict__ eb0) {
    int warp = (blockIdx.x * blockDim.x + threadIdx.x) >> 5;
    int lane = threadIdx.x & 31;
    if (warp >= BSZ*HDIM) return;
    int b = warp >> 9;
    int o = warp & 511;
    const float4* e4 = (const float4*)(g_e0 + b*HDIM);
    const float4* w4 = (const float4*)(W0 + (size_t)o*HDIM);
    float s = 0.f;
    #pragma unroll
    for (int it = 0; it < 4; it++) {
        float4 e = e4[lane + it*32];
        float4 w = w4[lane + it*32];
        s += e.x*w.x + e.y*w.y + e.z*w.z + e.w*w.w;
    }
    #pragma unroll
    for (int d = 16; d; d >>= 1) s += __shfl_xor_sync(0xffffffffu, s, d);
    if (lane == 0) g_em0[warp] = s + eb0[o];
}

// ---------------- layer-0 fused edge (no GEMM) + node update ----------------
__global__ void edge0_kernel(const int* __restrict__ mask) {
    int bi = blockIdx.x;
    int b  = bi >> 6;
    const float* nmB = g_nm + (size_t)b * NROI * HDIM;
    const float* nmi = g_nm + (size_t)bi * HDIM;
    __nv_bfloat16* dstp = g_ebuf[0] + (size_t)bi * NROI * HDIM;
    int o1 = threadIdx.x, o2 = threadIdx.x + 256;
    float nmv1 = nmi[o1], nmv2 = nmi[o2];
    float base1 = nmv1 + g_em0[b*HDIM + o1];
    float base2 = nmv2 + g_em0[b*HDIM + o2];
    float agg1 = 0.f, agg2 = 0.f;
    for (int j = 0; j < NROI; j++) {
        float m = (float)mask[bi*NROI + j];
        float nj1 = nmB[j*HDIM + o1];
        float nj2 = nmB[j*HDIM + o2];
        float e1 = leaky(base1 + nj1);
        float e2 = leaky(base2 + nj2);
        dstp[j*HDIM + o1] = __float2bfloat16(e1);
        dstp[j*HDIM + o2] = __float2bfloat16(e2);
        agg1 += e1 * nj1 * m;
        agg2 += e2 * nj2 * m;
    }
    float dn = g_denom[bi];
    float ns1 = g_ns[(size_t)bi*HDIM + o1] + leaky((nmv1 + agg1) / dn);
    float ns2 = g_ns[(size_t)bi*HDIM + o2] + leaky((nmv2 + agg2) / dn);
    g_ns[(size_t)bi*HDIM + o1] = ns1;
    g_ns[(size_t)bi*HDIM + o2] = ns2;
    g_ns16[(size_t)bi*HDIM + o1] = __float2bfloat16(ns1);
    g_ns16[(size_t)bi*HDIM + o2] = __float2bfloat16(ns2);
}

// ======================= pipelined bf16 MMA cores ===========================
#define KC    32
#define NIT   (HDIM/KC)     // 16
#define STRD  40            // smem row stride (elems); 20r%32 permutation -> conflict-free

// ---------------- nm GEMM (bf16 MMA): g_nm = ns16 @ nW[t]^T + nb ------------
__global__ __launch_bounds__(256) void nm_mma_kernel(
    int t, const float* __restrict__ bt)
{
    __shared__ __nv_bfloat16 As[2][64*STRD];
    __shared__ __nv_bfloat16 Bs[2][128*STRD];

    int tid  = threadIdx.x;
    int wid  = tid >> 5, lane = tid & 31;
    int wm   = wid & 3, wn = wid >> 2;
    int r0   = blockIdx.y * 64;
    int o0   = blockIdx.x * 128;

    const __nv_bfloat16* A  = g_ns16 + (size_t)r0 * HDIM;
    const __nv_bfloat16* Bw = g_nW16 + (size_t)t * HDIM * HDIM + (size_t)o0 * HDIM;

    float acc[8][4] = {};

    int arow = tid >> 2, acol = (tid & 3) * 8;   // A: 1x16B per thread
    int brow = tid >> 1, bcol = (tid & 1) * 16;  // B: 2x16B per thread

    // prologue: stage 0
    {
        cpa16(smem_u32(&As[0][arow*STRD + acol]), A + (size_t)arow*HDIM + acol);
        unsigned sB = smem_u32(&Bs[0][brow*STRD + bcol]);
        const __nv_bfloat16* gB = Bw + (size_t)brow*HDIM + bcol;
        cpa16(sB, gB); cpa16(sB+16, gB+8);
        asm volatile("cp.async.commit_group;");
    }

    for (int it = 0; it < NIT; it++) {
        asm volatile("cp.async.wait_group 0;");
        __syncthreads();
        if (it + 1 < NIT) {
            int st = (it + 1) & 1;
            int k0 = (it + 1) * KC;
            cpa16(smem_u32(&As[st][arow*STRD + acol]), A + (size_t)arow*HDIM + k0 + acol);
            unsigned sB = smem_u32(&Bs[st][brow*STRD + bcol]);
            const __nv_bfloat16* gB = Bw + (size_t)brow*HDIM + k0 + bcol;
            cpa16(sB, gB); cpa16(sB+16, gB+8);
            asm volatile("cp.async.commit_group;");
        }
        int st = it & 1;
        unsigned aBase = smem_u32(&As[st][(wm*16 + (lane & 15))*STRD + (lane >> 4)*8]);
        unsigned bBase = smem_u32(&Bs[st][(wn*64 + ((lane >> 4) << 3) + (lane & 7))*STRD
                                          + (((lane >> 3) & 1) << 3)]);
        #pragma unroll
        for (int ks = 0; ks < KC; ks += 16) {
            unsigned a0,a1,a2,a3;
            asm volatile("ldmatrix.sync.aligned.m8n8.x4.shared.b16 {%0,%1,%2,%3},[%4];"
                : "=r"(a0),"=r"(a1),"=r"(a2),"=r"(a3) : "r"(aBase + (unsigned)(ks*2)));
            #pragma unroll
            for (int p2 = 0; p2 < 4; p2++) {
                unsigned b0,b1,b2,b3;
                asm volatile("ldmatrix.sync.aligned.m8n8.x4.shared.b16 {%0,%1,%2,%3},[%4];"
                    : "=r"(b0),"=r"(b1),"=r"(b2),"=r"(b3)
                    : "r"(bBase + (unsigned)((p2*16*STRD + ks) * 2)));
                float* c0 = acc[p2*2];
                asm volatile("mma.sync.aligned.m16n8k16.row.col.f32.bf16.bf16.f32 "
                    "{%0,%1,%2,%3},{%4,%5,%6,%7},{%8,%9},{%0,%1,%2,%3};"
                    : "+f"(c0[0]),"+f"(c0[1]),"+f"(c0[2]),"+f"(c0[3])
                    : "r"(a0),"r"(a1),"r"(a2),"r"(a3),"r"(b0),"r"(b1));
                float* c1 = acc[p2*2+1];
                asm volatile("mma.sync.aligned.m16n8k16.row.col.f32.bf16.bf16.f32 "
                    "{%0,%1,%2,%3},{%4,%5,%6,%7},{%8,%9},{%0,%1,%2,%3};"
                    : "+f"(c1[0]),"+f"(c1[1]),"+f"(c1[2]),"+f"(c1[3])
                    : "r"(a0),"r"(a1),"r"(a2),"r"(a3),"r"(b2),"r"(b3));
            }
        }
        __syncthreads();
    }

    // epilogue: add bias, store fp32 nm
    int r1 = r0 + wm*16 + (lane >> 2);
    int r2 = r1 + 8;
    #pragma unroll
    for (int p = 0; p < 8; p++) {
        int o = o0 + wn*64 + p*8 + (lane & 3)*2;
        float2 bo = *(const float2*)(bt + o);
        float2 v1; v1.x = acc[p][0] + bo.x; v1.y = acc[p][1] + bo.y;
        float2 v2; v2.x = acc[p][2] + bo.x; v2.y = acc[p][3] + bo.y;
        *(float2*)(g_nm + (size_t)r1*HDIM + o) = v1;
        *(float2*)(g_nm + (size_t)r2*HDIM + o) = v2;
    }
}

// ---------------- fused edge GEMM (layers 1..4), 2-stage cp.async -----------
// Block: one (b,i), o-tile 128. GEMM 64(j) x 128(o) x 512(k). Fused epilogue:
// leaky + bf16 edge write + masked agg + node update (fp32 + bf16).
__global__ __launch_bounds__(256) void edge_mma_kernel(
    int t, const float* __restrict__ ebt, const int* __restrict__ mask,
    int src, int dst, int writeEdge)
{
    __shared__ __nv_bfloat16 As[2][64*STRD];
    __shared__ __nv_bfloat16 Bs[2][128*STRD];
    __shared__ float aggsm[4][128];

    int tid  = threadIdx.x;
    int wid  = tid >> 5, lane = tid & 31;
    int wm   = wid & 3, wn = wid >> 2;
    int bi   = blockIdx.y;
    int b    = bi >> 6;
    int o0   = blockIdx.x * 128;

    const __nv_bfloat16* A  = g_ebuf[src] + (size_t)bi * NROI * HDIM;
    const __nv_bfloat16* Bw = g_eW16 + (size_t)t * HDIM * HDIM + (size_t)o0 * HDIM;

    float acc[8][4] = {};

    int arow = tid >> 2, acol = (tid & 3) * 8;
    int brow = tid >> 1, bcol = (tid & 1) * 16;

    {
        cpa16(smem_u32(&As[0][arow*STRD + acol]), A + (size_t)arow*HDIM + acol);
        unsigned sB = smem_u32(&Bs[0][brow*STRD + bcol]);
        const __nv_bfloat16* gB = Bw + (size_t)brow*HDIM + bcol;
        cpa16(sB, gB); cpa16(sB+16, gB+8);
        asm volatile("cp.async.commit_group;");
    }

    for (int it = 0; it < NIT; it++) {
        asm volatile("cp.async.wait_group 0;");
        __syncthreads();
        if (it + 1 < NIT) {
            int st = (it + 1) & 1;
            int k0 = (it + 1) * KC;
            cpa16(smem_u32(&As[st][arow*STRD + acol]), A + (size_t)arow*HDIM + k0 + acol);
            unsigned sB = smem_u32(&Bs[st][brow*STRD + bcol]);
            const __nv_bfloat16* gB = Bw + (size_t)brow*HDIM + k0 + bcol;
            cpa16(sB, gB); cpa16(sB+16, gB+8);
            asm volatile("cp.async.commit_group;");
        }
        int st = it & 1;
        unsigned aBase = smem_u32(&As[st][(wm*16 + (lane & 15))*STRD + (lane >> 4)*8]);
        unsigned bBase = smem_u32(&Bs[st][(wn*64 + ((lane >> 4) << 3) + (lane & 7))*STRD
                                          + (((lane >> 3) & 1) << 3)]);
        #pragma unroll
        for (int ks = 0; ks < KC; ks += 16) {
            unsigned a0,a1,a2,a3;
            asm volatile("ldmatrix.sync.aligned.m8n8.x4.shared.b16 {%0,%1,%2,%3},[%4];"
                : "=r"(a0),"=r"(a1),"=r"(a2),"=r"(a3) : "r"(aBase + (unsigned)(ks*2)));
            #pragma unroll
            for (int p2 = 0; p2 < 4; p2++) {
                unsigned b0,b1,b2,b3;
                asm volatile("ldmatrix.sync.aligned.m8n8.x4.shared.b16 {%0,%1,%2,%3},[%4];"
                    : "=r"(b0),"=r"(b1),"=r"(b2),"=r"(b3)
                    : "r"(bBase + (unsigned)((p2*16*STRD + ks) * 2)));
                float* c0 = acc[p2*2];
                asm volatile("mma.sync.aligned.m16n8k16.row.col.f32.bf16.bf16.f32 "
                    "{%0,%1,%2,%3},{%4,%5,%6,%7},{%8,%9},{%0,%1,%2,%3};"
                    : "+f"(c0[0]),"+f"(c0[1]),"+f"(c0[2]),"+f"(c0[3])
                    : "r"(a0),"r"(a1),"r"(a2),"r"(a3),"r"(b0),"r"(b1));
                float* c1 = acc[p2*2+1];
                asm volatile("mma.sync.aligned.m16n8k16.row.col.f32.bf16.bf16.f32 "
                    "{%0,%1,%2,%3},{%4,%5,%6,%7},{%8,%9},{%0,%1,%2,%3};"
                    : "+f"(c1[0]),"+f"(c1[1]),"+f"(c1[2]),"+f"(c1[3])
                    : "r"(a0),"r"(a1),"r"(a2),"r"(a3),"r"(b2),"r"(b3));
            }
        }
        __syncthreads();
    }

    // ---- fused epilogue ----
    const float* nmB = g_nm + (size_t)b * NROI * HDIM;
    int rbase = wm*16 + (lane >> 2);
    int j1 = rbase, j2 = rbase + 8;
    float m1 = (float)mask[bi*NROI + j1];
    float m2 = (float)mask[bi*NROI + j2];
    __nv_bfloat16* dstp = g_ebuf[dst] + (size_t)bi * NROI * HDIM;

    #pragma unroll
    for (int p = 0; p < 8; p++) {
        int o = o0 + wn*64 + p*8 + (lane & 3)*2;
        float2 ni  = *(const float2*)(g_nm + (size_t)bi*HDIM + o);
        float2 ebv = *(const float2*)(ebt + o);
        float2 nj1 = *(const float2*)(nmB + (size_t)j1*HDIM + o);
        float2 nj2 = *(const float2*)(nmB + (size_t)j2*HDIM + o);
        float bx = ni.x + ebv.x, by = ni.y + ebv.y;
        float e00 = leaky(acc[p][0] + bx + nj1.x);
        float e01 = leaky(acc[p][1] + by + nj1.y);
        float e10 = leaky(acc[p][2] + bx + nj2.x);
        float e11 = leaky(acc[p][3] + by + nj2.y);
        if (writeEdge) {
            __nv_bfloat162 v1; v1.x = __float2bfloat16(e00); v1.y = __float2bfloat16(e01);
            __nv_bfloat162 v2; v2.x = __float2bfloat16(e10); v2.y = __float2bfloat16(e11);
            *(__nv_bfloat162*)(dstp + (size_t)j1*HDIM + o) = v1;
            *(__nv_bfloat162*)(dstp + (size_t)j2*HDIM + o) = v2;
        }
        float s0 = e00*nj1.x*m1 + e10*nj2.x*m2;
        float s1 = e01*nj1.y*m1 + e11*nj2.y*m2;
        #pragma unroll
        for (int d = 4; d <= 16; d <<= 1) {
            s0 += __shfl_xor_sync(0xffffffffu, s0, d);
            s1 += __shfl_xor_sync(0xffffffffu, s1, d);
        }
        if (lane < 4) {
            int oc = wn*64 + p*8 + lane*2;
            aggsm[wm][oc]   = s0;
            aggsm[wm][oc+1] = s1;
        }
    }
    __syncthreads();
    if (tid < 128) {
        float aggv = aggsm[0][tid] + aggsm[1][tid] + aggsm[2][tid] + aggsm[3][tid];
        int oo = o0 + tid;
        float nmv = g_nm[(size_t)bi*HDIM + oo];
        float x = (nmv + aggv) / g_denom[bi];
        float ns = g_ns[(size_t)bi*HDIM + oo] + leaky(x);
        g_ns[(size_t)bi*HDIM + oo] = ns;
        g_ns16[(size_t)bi*HDIM + oo] = __float2bfloat16(ns);
    }
}

// ---------------- output: concat broadcast of node_state --------------------
__global__ void out_kernel(float* __restrict__ out) {
    size_t f = (size_t)blockIdx.x * blockDim.x + threadIdx.x;
    size_t total4 = (size_t)BSZ*NROI*NROI*1024 / 4;
    if (f >= total4) return;
    size_t flat = f * 4;
    int c = (int)(flat & 1023);
    size_t bij = flat >> 10;
    int j = (int)(bij & 63);
    size_t bi = bij >> 6;            // b*64+i
    size_t b  = bi >> 6;
    const float* src = (c < 512)
        ? (g_ns + bi * HDIM + c)
        : (g_ns + (b*64 + j) * HDIM + (c - 512));
    *(float4*)(out + flat) = *(const float4*)src;
}

// ---------------- host launch ------------------------------------------------
extern "C" void kernel_launch(void* const* d_in, const int* in_sizes, int n_in,
                              void* d_out, int out_size) {
    const float* roi = (const float*)d_in[0];
    const float* img = (const float*)d_in[1];
    const float* nW  = (const float*)d_in[2];
    const float* nb  = (const float*)d_in[3];
    const float* eW  = (const float*)d_in[4];
    const float* eb  = (const float*)d_in[5];
    const int*   msk = (const int*)d_in[6];
    float* out = (float*)d_out;

    prep_kernel<<<512, 256>>>(roi, img, msk);
    convW_kernel<<<(NLAYER*HDIM*HDIM + 255)/256, 256>>>(eW, nW);

    for (int t = 0; t < NLAYER; t++) {
        nm_mma_kernel<<<dim3(4, 8), 256>>>(t, nb + (size_t)t*HDIM);
        if (t == 0) {
            em0_kernel<<<512, 256>>>(eW, eb);
            edge0_kernel<<<512, 256>>>(msk);
        } else {
            int dst = t & 1;
            int src = dst ^ 1;
            int we  = (t < NLAYER - 1) ? 1 : 0;   // last layer's edge_state unused
            edge_mma_kernel<<<dim3(4, 512), 256>>>(
                t, eb + (size_t)t*HDIM, msk, src, dst, we);
        }
    }

    out_kernel<<<32768, 256>>>(out);
}

// round 7
// speedup vs baseline: 1.6843x; 1.1004x over previous
#include <cuda_runtime.h>
#include <cuda_bf16.h>
#include <cstdint>

#define BSZ   8
#define NROI  64
#define HDIM  512
#define NLAYER 5
#define BI    (BSZ*NROI)                     // 512 (b,i) pairs

// ---------------- scratch (device globals; no allocation allowed) ----------
__device__ __nv_bfloat16 g_ebuf[2][(size_t)BSZ*NROI*NROI*HDIM]; // ping-pong edge_state (bf16)
__device__ __nv_bfloat16 g_eW16[(size_t)NLAYER*HDIM*HDIM];      // bf16 edge weights
__device__ __nv_bfloat16 g_nW16[(size_t)NLAYER*HDIM*HDIM];      // bf16 node weights
__device__ __nv_bfloat16 g_ns16[BI*HDIM];               // bf16 mirror of node_state
__device__ float g_nm[BI*HDIM];
__device__ float g_ns[BI*HDIM];
__device__ float g_denom[BI];
__device__ float g_em0[BSZ*HDIM];                       // layer-0 edge matvec (incl. bias)
__device__ float g_e0[BSZ*HDIM];                        // mean of img_featmap

__device__ __forceinline__ float leaky(float x) { return x >= 0.f ? x : 0.01f * x; }
__device__ __forceinline__ unsigned smem_u32(const void* p) {
    return (unsigned)__cvta_generic_to_shared(p);
}
__device__ __forceinline__ void cpa16(unsigned dst, const void* src) {
    asm volatile("cp.async.ca.shared.global [%0], [%1], 16;" :: "r"(dst), "l"(src));
}

// ---------------- prep: node_state copy (+bf16), e0 mean, denom -------------
__global__ void prep_kernel(const float* __restrict__ roi,
                            const float* __restrict__ img,
                            const int*  __restrict__ mask) {
    int idx = blockIdx.x * blockDim.x + threadIdx.x;
    int total = blockDim.x * gridDim.x;
    for (int i = idx; i < BI*HDIM; i += total) {
        float v = roi[i];
        g_ns[i] = v;
        g_ns16[i] = __float2bfloat16(v);
    }
    if (idx < BSZ*HDIM) {
        const float* p = img + (size_t)idx * 196;
        float s = 0.f;
        #pragma unroll 4
        for (int q = 0; q < 196; q++) s += p[q];
        g_e0[idx] = s * (1.0f/196.0f);
    }
    if (idx < BI) {
        const int* m = mask + idx * NROI;
        int s = 0;
        #pragma unroll
        for (int j = 0; j < NROI; j++) s += m[j];
        g_denom[idx] = (float)s + 1.0f;
    }
}

// ---------------- convert edge + node weights to bf16 -----------------------
__global__ void convW_kernel(const float* __restrict__ eW,
                             const float* __restrict__ nW) {
    int i = blockIdx.x * blockDim.x + threadIdx.x;
    const int half = NLAYER*HDIM*HDIM/2;
    if (i < half) {
        float2 v = ((const float2*)eW)[i];
        ((__nv_bfloat162*)g_eW16)[i] = __floats2bfloat162_rn(v.x, v.y);
    } else if (i < 2*half) {
        float2 v = ((const float2*)nW)[i - half];
        ((__nv_bfloat162*)g_nW16)[i - half] = __floats2bfloat162_rn(v.x, v.y);
    }
}

// ---------------- layer-0 edge matvec (float4 vectorized) -------------------
__global__ void em0_kernel(const float* __restrict__ W0,
                           const float* __restrict__ eb0) {
    int warp = (blockIdx.x * blockDim.x + threadIdx.x) >> 5;
    int lane = threadIdx.x & 31;
    if (warp >= BSZ*HDIM) return;
    int b = warp >> 9;
    int o = warp & 511;
    const float4* e4 = (const float4*)(g_e0 + b*HDIM);
    const float4* w4 = (const float4*)(W0 + (size_t)o*HDIM);
    float s = 0.f;
    #pragma unroll
    for (int it = 0; it < 4; it++) {
        float4 e = e4[lane + it*32];
        float4 w = w4[lane + it*32];
        s += e.x*w.x + e.y*w.y + e.z*w.z + e.w*w.w;
    }
    #pragma unroll
    for (int d = 16; d; d >>= 1) s += __shfl_xor_sync(0xffffffffu, s, d);
    if (lane == 0) g_em0[warp] = s + eb0[o];
}

// ---------------- layer-0 fused edge (no GEMM) + node update ----------------
__global__ void edge0_kernel(const int* __restrict__ mask) {
    int bi = blockIdx.x;
    int b  = bi >> 6;
    const float* nmB = g_nm + (size_t)b * NROI * HDIM;
    const float* nmi = g_nm + (size_t)bi * HDIM;
    __nv_bfloat16* dstp = g_ebuf[0] + (size_t)bi * NROI * HDIM;
    int o1 = threadIdx.x, o2 = threadIdx.x + 256;
    float nmv1 = nmi[o1], nmv2 = nmi[o2];
    float base1 = nmv1 + g_em0[b*HDIM + o1];
    float base2 = nmv2 + g_em0[b*HDIM + o2];
    float agg1 = 0.f, agg2 = 0.f;
    for (int j = 0; j < NROI; j++) {
        float m = (float)mask[bi*NROI + j];
        float nj1 = nmB[j*HDIM + o1];
        float nj2 = nmB[j*HDIM + o2];
        float e1 = leaky(base1 + nj1);
        float e2 = leaky(base2 + nj2);
        dstp[j*HDIM + o1] = __float2bfloat16(e1);
        dstp[j*HDIM + o2] = __float2bfloat16(e2);
        agg1 += e1 * nj1 * m;
        agg2 += e2 * nj2 * m;
    }
    float dn = g_denom[bi];
    float ns1 = g_ns[(size_t)bi*HDIM + o1] + leaky((nmv1 + agg1) / dn);
    float ns2 = g_ns[(size_t)bi*HDIM + o2] + leaky((nmv2 + agg2) / dn);
    g_ns[(size_t)bi*HDIM + o1] = ns1;
    g_ns[(size_t)bi*HDIM + o2] = ns2;
    g_ns16[(size_t)bi*HDIM + o1] = __float2bfloat16(ns1);
    g_ns16[(size_t)bi*HDIM + o2] = __float2bfloat16(ns2);
}

// ======================= nm GEMM (mma.sync, unchanged) ======================
#define KC    32
#define NIT   (HDIM/KC)     // 16
#define STRD  40

__global__ __launch_bounds__(256) void nm_mma_kernel(
    int t, const float* __restrict__ bt)
{
    __shared__ __nv_bfloat16 As[2][64*STRD];
    __shared__ __nv_bfloat16 Bs[2][128*STRD];

    int tid  = threadIdx.x;
    int wid  = tid >> 5, lane = tid & 31;
    int wm   = wid & 3, wn = wid >> 2;
    int r0   = blockIdx.y * 64;
    int o0   = blockIdx.x * 128;

    const __nv_bfloat16* A  = g_ns16 + (size_t)r0 * HDIM;
    const __nv_bfloat16* Bw = g_nW16 + (size_t)t * HDIM * HDIM + (size_t)o0 * HDIM;

    float acc[8][4] = {};

    int arow = tid >> 2, acol = (tid & 3) * 8;
    int brow = tid >> 1, bcol = (tid & 1) * 16;

    {
        cpa16(smem_u32(&As[0][arow*STRD + acol]), A + (size_t)arow*HDIM + acol);
        unsigned sB = smem_u32(&Bs[0][brow*STRD + bcol]);
        const __nv_bfloat16* gB = Bw + (size_t)brow*HDIM + bcol;
        cpa16(sB, gB); cpa16(sB+16, gB+8);
        asm volatile("cp.async.commit_group;");
    }

    for (int it = 0; it < NIT; it++) {
        asm volatile("cp.async.wait_group 0;");
        __syncthreads();
        if (it + 1 < NIT) {
            int st = (it + 1) & 1;
            int k0 = (it + 1) * KC;
            cpa16(smem_u32(&As[st][arow*STRD + acol]), A + (size_t)arow*HDIM + k0 + acol);
            unsigned sB = smem_u32(&Bs[st][brow*STRD + bcol]);
            const __nv_bfloat16* gB = Bw + (size_t)brow*HDIM + k0 + bcol;
            cpa16(sB, gB); cpa16(sB+16, gB+8);
            asm volatile("cp.async.commit_group;");
        }
        int st = it & 1;
        unsigned aBase = smem_u32(&As[st][(wm*16 + (lane & 15))*STRD + (lane >> 4)*8]);
        unsigned bBase = smem_u32(&Bs[st][(wn*64 + ((lane >> 4) << 3) + (lane & 7))*STRD
                                          + (((lane >> 3) & 1) << 3)]);
        #pragma unroll
        for (int ks = 0; ks < KC; ks += 16) {
            unsigned a0,a1,a2,a3;
            asm volatile("ldmatrix.sync.aligned.m8n8.x4.shared.b16 {%0,%1,%2,%3},[%4];"
                : "=r"(a0),"=r"(a1),"=r"(a2),"=r"(a3) : "r"(aBase + (unsigned)(ks*2)));
            #pragma unroll
            for (int p2 = 0; p2 < 4; p2++) {
                unsigned b0,b1,b2,b3;
                asm volatile("ldmatrix.sync.aligned.m8n8.x4.shared.b16 {%0,%1,%2,%3},[%4];"
                    : "=r"(b0),"=r"(b1),"=r"(b2),"=r"(b3)
                    : "r"(bBase + (unsigned)((p2*16*STRD + ks) * 2)));
                float* c0 = acc[p2*2];
                asm volatile("mma.sync.aligned.m16n8k16.row.col.f32.bf16.bf16.f32 "
                    "{%0,%1,%2,%3},{%4,%5,%6,%7},{%8,%9},{%0,%1,%2,%3};"
                    : "+f"(c0[0]),"+f"(c0[1]),"+f"(c0[2]),"+f"(c0[3])
                    : "r"(a0),"r"(a1),"r"(a2),"r"(a3),"r"(b0),"r"(b1));
                float* c1 = acc[p2*2+1];
                asm volatile("mma.sync.aligned.m16n8k16.row.col.f32.bf16.bf16.f32 "
                    "{%0,%1,%2,%3},{%4,%5,%6,%7},{%8,%9},{%0,%1,%2,%3};"
                    : "+f"(c1[0]),"+f"(c1[1]),"+f"(c1[2]),"+f"(c1[3])
                    : "r"(a0),"r"(a1),"r"(a2),"r"(a3),"r"(b2),"r"(b3));
            }
        }
        __syncthreads();
    }

    int r1 = r0 + wm*16 + (lane >> 2);
    int r2 = r1 + 8;
    #pragma unroll
    for (int p = 0; p < 8; p++) {
        int o = o0 + wn*64 + p*8 + (lane & 3)*2;
        float2 bo = *(const float2*)(bt + o);
        float2 v1; v1.x = acc[p][0] + bo.x; v1.y = acc[p][1] + bo.y;
        float2 v2; v2.x = acc[p][2] + bo.x; v2.y = acc[p][3] + bo.y;
        *(float2*)(g_nm + (size_t)r1*HDIM + o) = v1;
        *(float2*)(g_nm + (size_t)r2*HDIM + o) = v2;
    }
}

// ===== fused edge GEMM (layers 1..4): persistent-weight mma.sync ============
// Grid (4 o-tiles, 37 bi-groups) = 148 blocks (one wave). Each block keeps its
// 128x512 bf16 weight tile resident in smem and iterates over ~14 bi values;
// A (64x512) is double-buffered in two 256-k chunks with cp.async prefetch of
// the next bi. Inner k-loop is barrier-free. Fused epilogue: leaky + bf16
// edge write + masked agg + node update.
#define BSTR  520                      // B smem row stride (elems)
#define ASTR  264                      // A smem row stride (elems)
#define AKC   256                      // A chunk k size
#define SM_B  (128*BSTR*2)             // 133120 B
#define SM_A  (64*ASTR*2)              // 33792 B
#define EDSM  (SM_B + 2*SM_A)          // 200704 B dynamic

__global__ __launch_bounds__(256) void edge_pw_kernel(
    int t, const float* __restrict__ ebt, const int* __restrict__ mask,
    int src, int dst, int writeEdge)
{
    extern __shared__ __align__(16) unsigned char dsm[];
    __shared__ float aggsm[4][128];

    unsigned dB  = smem_u32(dsm);
    unsigned dA0 = dB + SM_B;
    unsigned dA1 = dA0 + SM_A;

    int tid  = threadIdx.x;
    int wid  = tid >> 5, lane = tid & 31;
    int wm   = wid & 3, wn = wid >> 2;
    int o0   = blockIdx.x * 128;
    int g    = blockIdx.y;             // 0..36
    int myStart = (g < 31) ? g*14 : 434 + (g-31)*13;
    int myCount = (g < 31) ? 14 : 13;

    const __nv_bfloat16* Bw = g_eW16 + (size_t)t * HDIM * HDIM + (size_t)o0 * HDIM;

    // ---- load resident B tile (128 x 512) ----
    #pragma unroll
    for (int it = 0; it < 32; it++) {
        int f = it*256 + tid;
        int row = f >> 6, seg = f & 63;            // 64 segs of 16B per row
        cpa16(dB + row*(BSTR*2) + seg*16, Bw + (size_t)row*HDIM + seg*8);
    }
    // ---- load first bi's A chunk 0 ----
    {
        const __nv_bfloat16* A = g_ebuf[src] + (size_t)myStart * NROI * HDIM;
        #pragma unroll
        for (int it = 0; it < 8; it++) {
            int f = it*256 + tid;
            int row = f >> 5, seg = f & 31;
            cpa16(dA0 + row*(ASTR*2) + seg*16, A + (size_t)row*HDIM + seg*8);
        }
    }
    asm volatile("cp.async.commit_group;");
    asm volatile("cp.async.wait_group 0;");
    __syncthreads();

    // ldmatrix bases
    unsigned aOffW = (unsigned)((wm*16 + (lane & 15))*(ASTR*2) + (lane >> 4)*16);
    unsigned bBase = dB + (unsigned)((wn*64 + ((lane >> 4) << 3) + (lane & 7))*(BSTR*2)
                                     + ((lane >> 3) & 1)*16);

    for (int ii = 0; ii < myCount; ii++) {
        int bi = myStart + ii;
        int b  = bi >> 6;
        const __nv_bfloat16* A = g_ebuf[src] + (size_t)bi * NROI * HDIM;

        float acc[8][4] = {};

        // issue A chunk1 (this bi) into dA1
        #pragma unroll
        for (int it = 0; it < 8; it++) {
            int f = it*256 + tid;
            int row = f >> 5, seg = f & 31;
            cpa16(dA1 + row*(ASTR*2) + seg*16, A + (size_t)row*HDIM + AKC + seg*8);
        }
        asm volatile("cp.async.commit_group;");

        // ---- compute chunk 0 (k 0..255), barrier-free ----
        #pragma unroll
        for (int ks = 0; ks < AKC; ks += 16) {
            unsigned a0,a1,a2,a3;
            asm volatile("ldmatrix.sync.aligned.m8n8.x4.shared.b16 {%0,%1,%2,%3},[%4];"
                : "=r"(a0),"=r"(a1),"=r"(a2),"=r"(a3) : "r"(dA0 + aOffW + (unsigned)(ks*2)));
            #pragma unroll
            for (int p2 = 0; p2 < 4; p2++) {
                unsigned b0,b1,b2,b3;
                asm volatile("ldmatrix.sync.aligned.m8n8.x4.shared.b16 {%0,%1,%2,%3},[%4];"
                    : "=r"(b0),"=r"(b1),"=r"(b2),"=r"(b3)
                    : "r"(bBase + (unsigned)(p2*16*(BSTR*2) + ks*2)));
                float* c0 = acc[p2*2];
                asm volatile("mma.sync.aligned.m16n8k16.row.col.f32.bf16.bf16.f32 "
                    "{%0,%1,%2,%3},{%4,%5,%6,%7},{%8,%9},{%0,%1,%2,%3};"
                    : "+f"(c0[0]),"+f"(c0[1]),"+f"(c0[2]),"+f"(c0[3])
                    : "r"(a0),"r"(a1),"r"(a2),"r"(a3),"r"(b0),"r"(b1));
                float* c1 = acc[p2*2+1];
                asm volatile("mma.sync.aligned.m16n8k16.row.col.f32.bf16.bf16.f32 "
                    "{%0,%1,%2,%3},{%4,%5,%6,%7},{%8,%9},{%0,%1,%2,%3};"
                    : "+f"(c1[0]),"+f"(c1[1]),"+f"(c1[2]),"+f"(c1[3])
                    : "r"(a0),"r"(a1),"r"(a2),"r"(a3),"r"(b2),"r"(b3));
            }
        }

        asm volatile("cp.async.wait_group 0;");
        __syncthreads();                 // chunk1 ready; all warps done with dA0

        // prefetch next bi's chunk0 into dA0
        if (ii + 1 < myCount) {
            const __nv_bfloat16* An = A + (size_t)NROI * HDIM;
            #pragma unroll
            for (int it = 0; it < 8; it++) {
                int f = it*256 + tid;
                int row = f >> 5, seg = f & 31;
                cpa16(dA0 + row*(ASTR*2) + seg*16, An + (size_t)row*HDIM + seg*8);
            }
            asm volatile("cp.async.commit_group;");
        }

        // ---- compute chunk 1 (k 256..511) ----
        #pragma unroll
        for (int ks = 0; ks < AKC; ks += 16) {
            unsigned a0,a1,a2,a3;
            asm volatile("ldmatrix.sync.aligned.m8n8.x4.shared.b16 {%0,%1,%2,%3},[%4];"
                : "=r"(a0),"=r"(a1),"=r"(a2),"=r"(a3) : "r"(dA1 + aOffW + (unsigned)(ks*2)));
            #pragma unroll
            for (int p2 = 0; p2 < 4; p2++) {
                unsigned b0,b1,b2,b3;
                asm volatile("ldmatrix.sync.aligned.m8n8.x4.shared.b16 {%0,%1,%2,%3},[%4];"
                    : "=r"(b0),"=r"(b1),"=r"(b2),"=r"(b3)
                    : "r"(bBase + (unsigned)(p2*16*(BSTR*2) + (AKC + ks)*2)));
                float* c0 = acc[p2*2];
                asm volatile("mma.sync.aligned.m16n8k16.row.col.f32.bf16.bf16.f32 "
                    "{%0,%1,%2,%3},{%4,%5,%6,%7},{%8,%9},{%0,%1,%2,%3};"
                    : "+f"(c0[0]),"+f"(c0[1]),"+f"(c0[2]),"+f"(c0[3])
                    : "r"(a0),"r"(a1),"r"(a2),"r"(a3),"r"(b0),"r"(b1));
                float* c1 = acc[p2*2+1];
                asm volatile("mma.sync.aligned.m16n8k16.row.col.f32.bf16.bf16.f32 "
                    "{%0,%1,%2,%3},{%4,%5,%6,%7},{%8,%9},{%0,%1,%2,%3};"
                    : "+f"(c1[0]),"+f"(c1[1]),"+f"(c1[2]),"+f"(c1[3])
                    : "r"(a0),"r"(a1),"r"(a2),"r"(a3),"r"(b2),"r"(b3));
            }
        }

        // ---- fused epilogue for this bi ----
        {
            const float* nmB = g_nm + (size_t)b * NROI * HDIM;
            int rbase = wm*16 + (lane >> 2);
            int j1 = rbase, j2 = rbase + 8;
            float m1 = (float)mask[bi*NROI + j1];
            float m2 = (float)mask[bi*NROI + j2];
            __nv_bfloat16* dstp = g_ebuf[dst] + (size_t)bi * NROI * HDIM;

            #pragma unroll
            for (int p = 0; p < 8; p++) {
                int o = o0 + wn*64 + p*8 + (lane & 3)*2;
                float2 ni  = *(const float2*)(g_nm + (size_t)bi*HDIM + o);
                float2 ebv = *(const float2*)(ebt + o);
                float2 nj1 = *(const float2*)(nmB + (size_t)j1*HDIM + o);
                float2 nj2 = *(const float2*)(nmB + (size_t)j2*HDIM + o);
                float bx = ni.x + ebv.x, by = ni.y + ebv.y;
                float e00 = leaky(acc[p][0] + bx + nj1.x);
                float e01 = leaky(acc[p][1] + by + nj1.y);
                float e10 = leaky(acc[p][2] + bx + nj2.x);
                float e11 = leaky(acc[p][3] + by + nj2.y);
                if (writeEdge) {
                    __nv_bfloat162 v1; v1.x = __float2bfloat16(e00); v1.y = __float2bfloat16(e01);
                    __nv_bfloat162 v2; v2.x = __float2bfloat16(e10); v2.y = __float2bfloat16(e11);
                    *(__nv_bfloat162*)(dstp + (size_t)j1*HDIM + o) = v1;
                    *(__nv_bfloat162*)(dstp + (size_t)j2*HDIM + o) = v2;
                }
                float s0 = e00*nj1.x*m1 + e10*nj2.x*m2;
                float s1 = e01*nj1.y*m1 + e11*nj2.y*m2;
                #pragma unroll
                for (int d = 4; d <= 16; d <<= 1) {
                    s0 += __shfl_xor_sync(0xffffffffu, s0, d);
                    s1 += __shfl_xor_sync(0xffffffffu, s1, d);
                }
                if (lane < 4) {
                    int oc = wn*64 + p*8 + lane*2;
                    aggsm[wm][oc]   = s0;
                    aggsm[wm][oc+1] = s1;
                }
            }
            __syncthreads();
            if (tid < 128) {
                float aggv = aggsm[0][tid] + aggsm[1][tid] + aggsm[2][tid] + aggsm[3][tid];
                int oo = o0 + tid;
                float nmv = g_nm[(size_t)bi*HDIM + oo];
                float x = (nmv + aggv) / g_denom[bi];
                float ns = g_ns[(size_t)bi*HDIM + oo] + leaky(x);
                g_ns[(size_t)bi*HDIM + oo] = ns;
                g_ns16[(size_t)bi*HDIM + oo] = __float2bfloat16(ns);
            }
        }

        // wait for next bi's chunk0 + retire epilogue smem use
        if (ii + 1 < myCount) {
            asm volatile("cp.async.wait_group 0;");
        }
        __syncthreads();
    }
}

// ---------------- output: concat broadcast of node_state --------------------
__global__ void out_kernel(float* __restrict__ out) {
    size_t f = (size_t)blockIdx.x * blockDim.x + threadIdx.x;
    size_t total4 = (size_t)BSZ*NROI*NROI*1024 / 4;
    if (f >= total4) return;
    size_t flat = f * 4;
    int c = (int)(flat & 1023);
    size_t bij = flat >> 10;
    int j = (int)(bij & 63);
    size_t bi = bij >> 6;            // b*64+i
    size_t b  = bi >> 6;
    const float* src = (c < 512)
        ? (g_ns + bi * HDIM + c)
        : (g_ns + (b*64 + j) * HDIM + (c - 512));
    *(float4*)(out + flat) = *(const float4*)src;
}

// ---------------- host launch ------------------------------------------------
extern "C" void kernel_launch(void* const* d_in, const int* in_sizes, int n_in,
                              void* d_out, int out_size) {
    const float* roi = (const float*)d_in[0];
    const float* img = (const float*)d_in[1];
    const float* nW  = (const float*)d_in[2];
    const float* nb  = (const float*)d_in[3];
    const float* eW  = (const float*)d_in[4];
    const float* eb  = (const float*)d_in[5];
    const int*   msk = (const int*)d_in[6];
    float* out = (float*)d_out;

    cudaFuncSetAttribute(edge_pw_kernel,
                         cudaFuncAttributeMaxDynamicSharedMemorySize, EDSM);

    prep_kernel<<<512, 256>>>(roi, img, msk);
    convW_kernel<<<(NLAYER*HDIM*HDIM + 255)/256, 256>>>(eW, nW);

    for (int t = 0; t < NLAYER; t++) {
        nm_mma_kernel<<<dim3(4, 8), 256>>>(t, nb + (size_t)t*HDIM);
        if (t == 0) {
            em0_kernel<<<512, 256>>>(eW, eb);
            edge0_kernel<<<512, 256>>>(msk);
        } else {
            int dst = t & 1;
            int src = dst ^ 1;
            int we  = (t < NLAYER - 1) ? 1 : 0;
            edge_pw_kernel<<<dim3(4, 37), 256, EDSM>>>(
                t, eb + (size_t)t*HDIM, msk, src, dst, we);
        }
    }

    out_kernel<<<32768, 256>>>(out);
}